// round 3
// baseline (speedup 1.0000x reference)
#include <cuda_runtime.h>
#include <cstdint>

#define D 1024
#define B_TOK 16384
#define E_EXP 8
#define NSLOT (2 * B_TOK)

// ---------------- scratch: __device__ globals (no allocations allowed) ----------------
__device__ float  g_Wog[D * E_EXP];        // Wo @ Wg
__device__ float  g_Wvog[D * E_EXP];       // Wv @ (Wo @ Wg)
__device__ float  g_beff[E_EXP];           // bv@Wog + bo@Wg + bg
__device__ int    g_tok_e[2 * B_TOK];      // per-token top-2 expert ids
__device__ float  g_tok_w[2 * B_TOK];      // per-token renormalized weights
__device__ int    g_tok_slot[2 * B_TOK];   // per-token slot indices
__device__ int    g_counts[E_EXP];
__device__ int    g_offsets[E_EXP];
__device__ int    g_cursor[E_EXP];
__device__ double g_imp[E_EXP];
__device__ int    g_slot_tok[NSLOT];
__device__ float  g_slot_w[NSLOT];
__device__ float  g_h1[(size_t)NSLOT * D]; // expert hidden (silu output), 128 MB
__device__ float  g_h2[(size_t)NSLOT * D]; // expert output (scaled), 128 MB

// ---------------- tf32 helpers ----------------
__device__ __forceinline__ uint32_t f2tf(float x) {
    uint32_t r;
    asm("cvt.rna.tf32.f32 %0, %1;" : "=r"(r) : "f"(x));
    return r;
}
__device__ __forceinline__ void mma_tf32(float* d, const uint32_t* a, const uint32_t* b) {
    asm("mma.sync.aligned.m16n8k8.row.col.f32.tf32.tf32.f32 "
        "{%0,%1,%2,%3},{%4,%5,%6,%7},{%8,%9},{%0,%1,%2,%3};"
        : "+f"(d[0]), "+f"(d[1]), "+f"(d[2]), "+f"(d[3])
        : "r"(a[0]), "r"(a[1]), "r"(a[2]), "r"(a[3]), "r"(b[0]), "r"(b[1]));
}

// ---------------- zero the per-call accumulators ----------------
__global__ void k_zero() {
    int t = threadIdx.x;
    if (t < E_EXP) { g_counts[t] = 0; g_cursor[t] = 0; g_imp[t] = 0.0; }
}

// ---------------- out[r][e] = sum_k A[r*D+k] * Bm[k*8+e]  (D x 8 result) ----------------
__global__ __launch_bounds__(256) void k_mat_small(const float* __restrict__ A,
                                                   const float* __restrict__ BmArg,
                                                   int which) {
    const float* Bm = (which == 0) ? BmArg : g_Wog;
    float* out = (which == 0) ? g_Wog : g_Wvog;
    int r = blockIdx.x;
    float acc[8];
#pragma unroll
    for (int e = 0; e < 8; e++) acc[e] = 0.f;
    for (int k = threadIdx.x; k < D; k += 256) {
        float a = A[(size_t)r * D + k];
        const float4* b4 = reinterpret_cast<const float4*>(Bm + (size_t)k * 8);
        float4 b0 = b4[0], b1 = b4[1];
        acc[0] += a * b0.x; acc[1] += a * b0.y; acc[2] += a * b0.z; acc[3] += a * b0.w;
        acc[4] += a * b1.x; acc[5] += a * b1.y; acc[6] += a * b1.z; acc[7] += a * b1.w;
    }
#pragma unroll
    for (int off = 16; off > 0; off >>= 1)
#pragma unroll
        for (int e = 0; e < 8; e++) acc[e] += __shfl_xor_sync(0xFFFFFFFFu, acc[e], off);
    __shared__ float sred[8][8];
    int warp = threadIdx.x >> 5, lane = threadIdx.x & 31;
    if (lane == 0)
#pragma unroll
        for (int e = 0; e < 8; e++) sred[warp][e] = acc[e];
    __syncthreads();
    if (threadIdx.x < 8) {
        float s = 0.f;
#pragma unroll
        for (int w = 0; w < 8; w++) s += sred[w][threadIdx.x];
        out[(size_t)r * 8 + threadIdx.x] = s;
    }
}

// ---------------- beff[e] = bv@Wog + bo@Wg + bg ----------------
__global__ __launch_bounds__(256) void k_beff(const float* __restrict__ bv,
                                              const float* __restrict__ bo,
                                              const float* __restrict__ Wg,
                                              const float* __restrict__ bg) {
    float acc[8];
#pragma unroll
    for (int e = 0; e < 8; e++) acc[e] = 0.f;
    for (int k = threadIdx.x; k < D; k += 256) {
        float a = bv[k], b = bo[k];
        const float4* w4 = reinterpret_cast<const float4*>(g_Wog + (size_t)k * 8);
        const float4* g4 = reinterpret_cast<const float4*>(Wg + (size_t)k * 8);
        float4 w0 = w4[0], w1 = w4[1], g0 = g4[0], g1 = g4[1];
        acc[0] += a * w0.x + b * g0.x; acc[1] += a * w0.y + b * g0.y;
        acc[2] += a * w0.z + b * g0.z; acc[3] += a * w0.w + b * g0.w;
        acc[4] += a * w1.x + b * g1.x; acc[5] += a * w1.y + b * g1.y;
        acc[6] += a * w1.z + b * g1.z; acc[7] += a * w1.w + b * g1.w;
    }
#pragma unroll
    for (int off = 16; off > 0; off >>= 1)
#pragma unroll
        for (int e = 0; e < 8; e++) acc[e] += __shfl_xor_sync(0xFFFFFFFFu, acc[e], off);
    __shared__ float sred[8][8];
    int warp = threadIdx.x >> 5, lane = threadIdx.x & 31;
    if (lane == 0)
#pragma unroll
        for (int e = 0; e < 8; e++) sred[warp][e] = acc[e];
    __syncthreads();
    if (threadIdx.x < 8) {
        float s = 0.f;
#pragma unroll
        for (int w = 0; w < 8; w++) s += sred[w][threadIdx.x];
        g_beff[threadIdx.x] = s + bg[threadIdx.x];
    }
}

// ---------------- gating: logits, softmax, top-2, counts, importance ----------------
__global__ __launch_bounds__(256) void k_gate(const float* __restrict__ q,
                                              float* __restrict__ gate_out) {
    int warp = threadIdx.x >> 5, lane = threadIdx.x & 31;
    int b = blockIdx.x * 8 + warp;
    const float* qrow = q + (size_t)b * D;
    float acc[8];
#pragma unroll
    for (int e = 0; e < 8; e++) acc[e] = 0.f;
#pragma unroll 4
    for (int i = 0; i < 32; i++) {
        int k = i * 32 + lane;
        float qa = qrow[k];
        const float4* w4 = reinterpret_cast<const float4*>(g_Wvog + (size_t)k * 8);
        float4 w0 = w4[0], w1 = w4[1];
        acc[0] += qa * w0.x; acc[1] += qa * w0.y; acc[2] += qa * w0.z; acc[3] += qa * w0.w;
        acc[4] += qa * w1.x; acc[5] += qa * w1.y; acc[6] += qa * w1.z; acc[7] += qa * w1.w;
    }
#pragma unroll
    for (int off = 16; off > 0; off >>= 1)
#pragma unroll
        for (int e = 0; e < 8; e++) acc[e] += __shfl_xor_sync(0xFFFFFFFFu, acc[e], off);

    __shared__ double simp[8];
    if (threadIdx.x < 8) simp[threadIdx.x] = 0.0;
    __syncthreads();

    if (lane == 0) {
        float l[8];
#pragma unroll
        for (int e = 0; e < 8; e++) l[e] = acc[e] + g_beff[e];
        float m = l[0];
#pragma unroll
        for (int e = 1; e < 8; e++) m = fmaxf(m, l[e]);
        float ex[8], Z = 0.f;
#pragma unroll
        for (int e = 0; e < 8; e++) { ex[e] = expf(l[e] - m); Z += ex[e]; }
        float p[8];
        float invZ = 1.f / Z;
#pragma unroll
        for (int e = 0; e < 8; e++) p[e] = ex[e] * invZ;
#pragma unroll
        for (int e = 0; e < 8; e++) gate_out[(size_t)b * 8 + e] = p[e];

        int e1 = 0;
#pragma unroll
        for (int e = 1; e < 8; e++) if (p[e] > p[e1]) e1 = e;
        int e2 = (e1 == 0) ? 1 : 0;
#pragma unroll
        for (int e = 0; e < 8; e++) if (e != e1 && p[e] > p[e2]) e2 = e;
        float t = expf(p[e2] - p[e1]);
        float inv = 1.f / (1.f + t);
        g_tok_e[2 * b] = e1;  g_tok_e[2 * b + 1] = e2;
        g_tok_w[2 * b] = inv; g_tok_w[2 * b + 1] = t * inv;
        atomicAdd(&g_counts[e1], 1);
        atomicAdd(&g_counts[e2], 1);
#pragma unroll
        for (int e = 0; e < 8; e++) atomicAdd(&simp[e], (double)p[e]);
    }
    __syncthreads();
    if (threadIdx.x < 8) atomicAdd(&g_imp[threadIdx.x], simp[threadIdx.x]);
}

// ---------------- exclusive scan over 8 counts ----------------
__global__ void k_scan() {
    if (threadIdx.x == 0) {
        int o = 0;
#pragma unroll
        for (int e = 0; e < 8; e++) { g_offsets[e] = o; o += g_counts[e]; }
    }
}

// ---------------- scatter tokens into expert groups ----------------
__global__ __launch_bounds__(256) void k_scatter() {
    int b = blockIdx.x * 256 + threadIdx.x;
    if (b >= B_TOK) return;
#pragma unroll
    for (int j = 0; j < 2; j++) {
        int e = g_tok_e[2 * b + j];
        int s = g_offsets[e] + atomicAdd(&g_cursor[e], 1);
        g_slot_tok[s] = b;
        g_slot_w[s] = g_tok_w[2 * b + j];
        g_tok_slot[2 * b + j] = s;
    }
}

// ---------------- grouped 3xTF32 tensor-core GEMM ----------------
// 128x128 CTA tile, BK=16, 256 threads = 8 warps (2 M x 4 N), warp tile 64x32.
// A smem: k-permuted (0,4,1,5,2,6,3,7) within each 8-group, stride 24 -> LDS.64 frags.
// B smem: [k][n] stride 136 -> conflict-free LDS.32 frags.
// MODE 1: g_h1[goff+r,:] = silu( x[slot_tok[goff+r],:] @ W1[e] + b1[e] )
// MODE 2: g_h2[goff+r,:] = slot_w[goff+r] * ( g_h1[goff+r,:] @ W2[e] + b2[e] )
#define SA 24
#define SB 136

template <int MODE>
__global__ __launch_bounds__(256) void k_gemm(const float* __restrict__ X,
                                              const float* __restrict__ Wbase,
                                              const float* __restrict__ bbase) {
    __shared__ float As_hi[128][SA], As_lo[128][SA];
    __shared__ float Bs_hi[16][SB],  Bs_lo[16][SB];

    int e = blockIdx.z;
    int M = g_counts[e];
    int m0 = blockIdx.y * 128;
    if (m0 >= M) return;
    int n0 = blockIdx.x * 128;
    int goff = g_offsets[e];
    const float* Wp = Wbase + (size_t)e * D * D;
    const float* bp = bbase + (size_t)e * D;

    int tid = threadIdx.x;
    int lane = tid & 31, warp = tid >> 5;
    int g = lane >> 2, c4 = lane & 3;
    int wm = warp >> 2, wn = warp & 3;

    // global A loader: row ar, k-half kh (8 floats as 2 float4)
    int ar = tid >> 1;
    int kh = (tid & 1) * 8;
    int r = m0 + ar; if (r > M - 1) r = M - 1;
    const float* arow;
    if (MODE == 1) arow = X + (size_t)g_slot_tok[goff + r] * D + kh;
    else           arow = g_h1 + (size_t)(goff + r) * D + kh;
    // global B loader: k-row bk, 8 cols at bn (2 float4)
    int bk = tid >> 4;
    int bn = (tid & 15) * 8;
    const float* bptr = Wp + (size_t)bk * D + n0 + bn;

    float acc[4][4][4];
#pragma unroll
    for (int mt = 0; mt < 4; mt++)
#pragma unroll
        for (int nt = 0; nt < 4; nt++)
#pragma unroll
            for (int i = 0; i < 4; i++) acc[mt][nt][i] = 0.f;

    float4 fa0, fa1, fb0, fb1;
    // prologue: load tile 0, convert+store, sync
    fa0 = *reinterpret_cast<const float4*>(arow);
    fa1 = *reinterpret_cast<const float4*>(arow + 4);
    fb0 = *reinterpret_cast<const float4*>(bptr);
    fb1 = *reinterpret_cast<const float4*>(bptr + 4);
    {
        float av[8] = {fa0.x, fa0.y, fa0.z, fa0.w, fa1.x, fa1.y, fa1.z, fa1.w};
#pragma unroll
        for (int i = 0; i < 4; i++) {
            uint32_t h = f2tf(av[i]);
            As_hi[ar][kh + 2 * i] = __uint_as_float(h);
            As_lo[ar][kh + 2 * i] = __uint_as_float(f2tf(av[i] - __uint_as_float(h)));
            uint32_t h2 = f2tf(av[i + 4]);
            As_hi[ar][kh + 2 * i + 1] = __uint_as_float(h2);
            As_lo[ar][kh + 2 * i + 1] = __uint_as_float(f2tf(av[i + 4] - __uint_as_float(h2)));
        }
        float bvv[8] = {fb0.x, fb0.y, fb0.z, fb0.w, fb1.x, fb1.y, fb1.z, fb1.w};
#pragma unroll
        for (int i = 0; i < 8; i++) {
            uint32_t h = f2tf(bvv[i]);
            Bs_hi[bk][bn + i] = __uint_as_float(h);
            Bs_lo[bk][bn + i] = __uint_as_float(f2tf(bvv[i] - __uint_as_float(h)));
        }
    }
    __syncthreads();

    const int NT = D / 16;
    for (int t = 0; t < NT; t++) {
        if (t + 1 < NT) {
            fa0 = *reinterpret_cast<const float4*>(arow + (t + 1) * 16);
            fa1 = *reinterpret_cast<const float4*>(arow + (t + 1) * 16 + 4);
            fb0 = *reinterpret_cast<const float4*>(bptr + (size_t)(t + 1) * 16 * D);
            fb1 = *reinterpret_cast<const float4*>(bptr + (size_t)(t + 1) * 16 * D + 4);
        }
#pragma unroll
        for (int ks = 0; ks < 2; ks++) {
            int kb = ks * 8;
            uint32_t bh[4][2], bl[4][2];
#pragma unroll
            for (int nt = 0; nt < 4; nt++) {
                int colb = wn * 32 + nt * 8 + g;
                bh[nt][0] = __float_as_uint(Bs_hi[kb + c4][colb]);
                bh[nt][1] = __float_as_uint(Bs_hi[kb + c4 + 4][colb]);
                bl[nt][0] = __float_as_uint(Bs_lo[kb + c4][colb]);
                bl[nt][1] = __float_as_uint(Bs_lo[kb + c4 + 4][colb]);
            }
#pragma unroll
            for (int mt = 0; mt < 4; mt++) {
                int row = wm * 64 + mt * 16 + g;
                float2 h0 = *reinterpret_cast<const float2*>(&As_hi[row][kb + 2 * c4]);
                float2 h1 = *reinterpret_cast<const float2*>(&As_hi[row + 8][kb + 2 * c4]);
                float2 l0 = *reinterpret_cast<const float2*>(&As_lo[row][kb + 2 * c4]);
                float2 l1 = *reinterpret_cast<const float2*>(&As_lo[row + 8][kb + 2 * c4]);
                uint32_t ah[4] = {__float_as_uint(h0.x), __float_as_uint(h1.x),
                                  __float_as_uint(h0.y), __float_as_uint(h1.y)};
                uint32_t al[4] = {__float_as_uint(l0.x), __float_as_uint(l1.x),
                                  __float_as_uint(l0.y), __float_as_uint(l1.y)};
#pragma unroll
                for (int nt = 0; nt < 4; nt++) {
                    mma_tf32(acc[mt][nt], ah, bh[nt]);
                    mma_tf32(acc[mt][nt], ah, bl[nt]);
                    mma_tf32(acc[mt][nt], al, bh[nt]);
                }
            }
        }
        __syncthreads();
        if (t + 1 < NT) {
            float av[8] = {fa0.x, fa0.y, fa0.z, fa0.w, fa1.x, fa1.y, fa1.z, fa1.w};
#pragma unroll
            for (int i = 0; i < 4; i++) {
                uint32_t h = f2tf(av[i]);
                As_hi[ar][kh + 2 * i] = __uint_as_float(h);
                As_lo[ar][kh + 2 * i] = __uint_as_float(f2tf(av[i] - __uint_as_float(h)));
                uint32_t h2 = f2tf(av[i + 4]);
                As_hi[ar][kh + 2 * i + 1] = __uint_as_float(h2);
                As_lo[ar][kh + 2 * i + 1] = __uint_as_float(f2tf(av[i + 4] - __uint_as_float(h2)));
            }
            float bvv[8] = {fb0.x, fb0.y, fb0.z, fb0.w, fb1.x, fb1.y, fb1.z, fb1.w};
#pragma unroll
            for (int i = 0; i < 8; i++) {
                uint32_t h = f2tf(bvv[i]);
                Bs_hi[bk][bn + i] = __uint_as_float(h);
                Bs_lo[bk][bn + i] = __uint_as_float(f2tf(bvv[i] - __uint_as_float(h)));
            }
            __syncthreads();
        }
    }

    // epilogue: acc regs c0,c1 -> (row0, col..col+1); c2,c3 -> (row0+8, ...)
    float* Cbase = (MODE == 1) ? g_h1 : g_h2;
#pragma unroll
    for (int nt = 0; nt < 4; nt++) {
        int col = n0 + wn * 32 + nt * 8 + 2 * c4;
        float2 bb = *reinterpret_cast<const float2*>(bp + col);
#pragma unroll
        for (int mt = 0; mt < 4; mt++) {
            int r0 = m0 + wm * 64 + mt * 16 + g;
#pragma unroll
            for (int half = 0; half < 2; half++) {
                int gr = r0 + half * 8;
                if (gr >= M) continue;
                float z0 = acc[mt][nt][2 * half]     + bb.x;
                float z1 = acc[mt][nt][2 * half + 1] + bb.y;
                float v0, v1;
                if (MODE == 1) {
                    v0 = z0 / (1.f + expf(-z0));
                    v1 = z1 / (1.f + expf(-z1));
                } else {
                    float wr = g_slot_w[goff + gr];
                    v0 = wr * z0;
                    v1 = wr * z1;
                }
                *reinterpret_cast<float2*>(Cbase + (size_t)(goff + gr) * D + col) =
                    make_float2(v0, v1);
            }
        }
    }
}

// ---------------- combine: y[b] = h2[slot(b,0)] + h2[slot(b,1)] ----------------
__global__ __launch_bounds__(256) void k_combine(float* __restrict__ y) {
    int idx = blockIdx.x * 256 + threadIdx.x;
    int b = idx >> 8;
    int c = idx & 255;
    const float4* h2 = reinterpret_cast<const float4*>(g_h2);
    float4 u = h2[(size_t)g_tok_slot[2 * b] * 256 + c];
    float4 v = h2[(size_t)g_tok_slot[2 * b + 1] * 256 + c];
    reinterpret_cast<float4*>(y)[idx] = make_float4(u.x + v.x, u.y + v.y, u.z + v.z, u.w + v.w);
}

// ---------------- importance loss ----------------
__global__ void k_loss(float* __restrict__ out) {
    if (threadIdx.x == 0) {
        double s = 0.0;
#pragma unroll
        for (int e = 0; e < 8; e++) s += g_imp[e];
        double mean = s / 8.0;
        double var = 0.0;
#pragma unroll
        for (int e = 0; e < 8; e++) { double d = g_imp[e] - mean; var += d * d; }
        var /= 7.0;
        out[0] = (float)(0.01 * var / (mean * mean));
    }
}

extern "C" void kernel_launch(void* const* d_in, const int* in_sizes, int n_in,
                              void* d_out, int out_size) {
    const float* x  = (const float*)d_in[0];
    const float* q  = (const float*)d_in[1];
    const float* Wv = (const float*)d_in[2];
    const float* bv = (const float*)d_in[3];
    const float* Wo = (const float*)d_in[4];
    const float* bo = (const float*)d_in[5];
    const float* Wg = (const float*)d_in[6];
    const float* bg = (const float*)d_in[7];
    const float* W1 = (const float*)d_in[8];
    const float* b1 = (const float*)d_in[9];
    const float* W2 = (const float*)d_in[10];
    const float* b2 = (const float*)d_in[11];

    float* y        = (float*)d_out;
    float* gate_out = y + (size_t)B_TOK * D;
    float* loss_out = gate_out + (size_t)B_TOK * E_EXP;

    k_zero<<<1, 32>>>();
    k_mat_small<<<D, 256>>>(Wo, Wg, 0);        // g_Wog  = Wo @ Wg
    k_mat_small<<<D, 256>>>(Wv, nullptr, 1);   // g_Wvog = Wv @ g_Wog
    k_beff<<<1, 256>>>(bv, bo, Wg, bg);
    k_gate<<<B_TOK / 8, 256>>>(q, gate_out);
    k_scan<<<1, 32>>>();
    k_scatter<<<B_TOK / 256, 256>>>();
    k_gemm<1><<<dim3(D / 128, B_TOK / 128, E_EXP), 256>>>(x, W1, b1);
    k_gemm<2><<<dim3(D / 128, B_TOK / 128, E_EXP), 256>>>(nullptr, W2, b2);
    k_combine<<<(B_TOK * D / 4) / 256, 256>>>(y);
    k_loss<<<1, 32>>>(loss_out);
}

// round 4
// speedup vs baseline: 3.1121x; 3.1121x over previous
#include <cuda_runtime.h>
#include <cuda_bf16.h>
#include <cstdint>

#define D 1024
#define B_TOK 16384
#define E_EXP 8
#define NSLOT (2 * B_TOK)
#define NKT (D / 16)          // 64 k-tiles
#define STAGES 5
#define SMEM_BYTES (STAGES * 16384)

// ---------------- scratch: __device__ globals (no allocations allowed) ----------------
__device__ float  g_Wog[D * E_EXP];
__device__ float  g_Wvog[D * E_EXP];
__device__ float  g_beff[E_EXP];
__device__ int    g_tok_e[2 * B_TOK];
__device__ float  g_tok_w[2 * B_TOK];
__device__ int    g_tok_slot[2 * B_TOK];
__device__ int    g_counts[E_EXP];
__device__ int    g_offsets[E_EXP];
__device__ int    g_cursor[E_EXP];
__device__ double g_imp[E_EXP];
__device__ int    g_slot_tok[NSLOT];
__device__ float  g_slot_w[NSLOT];

// bf16 split planes (hi/lo). x planes in pair-permuted k layout.
__device__ __align__(256) __nv_bfloat16 g_xhi[(size_t)B_TOK * D];
__device__ __align__(256) __nv_bfloat16 g_xlo[(size_t)B_TOK * D];
// weights transposed: [e][kt][n][16] pair-permuted k within the 16
__device__ __align__(256) __nv_bfloat16 g_w1hi[(size_t)E_EXP * NKT * D * 16];
__device__ __align__(256) __nv_bfloat16 g_w1lo[(size_t)E_EXP * NKT * D * 16];
__device__ __align__(256) __nv_bfloat16 g_w2hi[(size_t)E_EXP * NKT * D * 16];
__device__ __align__(256) __nv_bfloat16 g_w2lo[(size_t)E_EXP * NKT * D * 16];
// h1 planes (silu output), pair-permuted layout, indexed by slot
__device__ __align__(256) __nv_bfloat16 g_h1hi[(size_t)NSLOT * D];
__device__ __align__(256) __nv_bfloat16 g_h1lo[(size_t)NSLOT * D];
__device__ __align__(256) float g_h2[(size_t)NSLOT * D];

// pair-permuted position of k within a 16-group: pairs stored (0,4,1,5,2,6,3,7)
__device__ __forceinline__ int perm16(int k) {
    int p = k >> 1;
    return (((p & 3) * 2 + (p >> 2)) << 1) + (k & 1);
}

__device__ __forceinline__ void cpa16(uint32_t saddr, const void* g) {
    asm volatile("cp.async.cg.shared.global [%0], [%1], 16;" :: "r"(saddr), "l"(g));
}
__device__ __forceinline__ void mma_bf16(float* d, const uint32_t* a, const uint32_t* b) {
    asm("mma.sync.aligned.m16n8k16.row.col.f32.bf16.bf16.f32 "
        "{%0,%1,%2,%3},{%4,%5,%6,%7},{%8,%9},{%0,%1,%2,%3};"
        : "+f"(d[0]), "+f"(d[1]), "+f"(d[2]), "+f"(d[3])
        : "r"(a[0]), "r"(a[1]), "r"(a[2]), "r"(a[3]), "r"(b[0]), "r"(b[1]));
}

// ---------------- zero ----------------
__global__ void k_zero() {
    int t = threadIdx.x;
    if (t < E_EXP) { g_counts[t] = 0; g_cursor[t] = 0; g_imp[t] = 0.0; }
}

// ---------------- small mats for gating (fp32, unchanged from R2) ----------------
__global__ __launch_bounds__(256) void k_mat_small(const float* __restrict__ A,
                                                   const float* __restrict__ BmArg,
                                                   int which) {
    const float* Bm = (which == 0) ? BmArg : g_Wog;
    float* out = (which == 0) ? g_Wog : g_Wvog;
    int r = blockIdx.x;
    float acc[8];
#pragma unroll
    for (int e = 0; e < 8; e++) acc[e] = 0.f;
    for (int k = threadIdx.x; k < D; k += 256) {
        float a = A[(size_t)r * D + k];
        const float4* b4 = reinterpret_cast<const float4*>(Bm + (size_t)k * 8);
        float4 b0 = b4[0], b1 = b4[1];
        acc[0] += a * b0.x; acc[1] += a * b0.y; acc[2] += a * b0.z; acc[3] += a * b0.w;
        acc[4] += a * b1.x; acc[5] += a * b1.y; acc[6] += a * b1.z; acc[7] += a * b1.w;
    }
#pragma unroll
    for (int off = 16; off > 0; off >>= 1)
#pragma unroll
        for (int e = 0; e < 8; e++) acc[e] += __shfl_xor_sync(0xFFFFFFFFu, acc[e], off);
    __shared__ float sred[8][8];
    int warp = threadIdx.x >> 5, lane = threadIdx.x & 31;
    if (lane == 0)
#pragma unroll
        for (int e = 0; e < 8; e++) sred[warp][e] = acc[e];
    __syncthreads();
    if (threadIdx.x < 8) {
        float s = 0.f;
#pragma unroll
        for (int w = 0; w < 8; w++) s += sred[w][threadIdx.x];
        out[(size_t)r * 8 + threadIdx.x] = s;
    }
}

__global__ __launch_bounds__(256) void k_beff(const float* __restrict__ bv,
                                              const float* __restrict__ bo,
                                              const float* __restrict__ Wg,
                                              const float* __restrict__ bg) {
    float acc[8];
#pragma unroll
    for (int e = 0; e < 8; e++) acc[e] = 0.f;
    for (int k = threadIdx.x; k < D; k += 256) {
        float a = bv[k], b = bo[k];
        const float4* w4 = reinterpret_cast<const float4*>(g_Wog + (size_t)k * 8);
        const float4* g4 = reinterpret_cast<const float4*>(Wg + (size_t)k * 8);
        float4 w0 = w4[0], w1 = w4[1], g0 = g4[0], g1 = g4[1];
        acc[0] += a * w0.x + b * g0.x; acc[1] += a * w0.y + b * g0.y;
        acc[2] += a * w0.z + b * g0.z; acc[3] += a * w0.w + b * g0.w;
        acc[4] += a * w1.x + b * g1.x; acc[5] += a * w1.y + b * g1.y;
        acc[6] += a * w1.z + b * g1.z; acc[7] += a * w1.w + b * g1.w;
    }
#pragma unroll
    for (int off = 16; off > 0; off >>= 1)
#pragma unroll
        for (int e = 0; e < 8; e++) acc[e] += __shfl_xor_sync(0xFFFFFFFFu, acc[e], off);
    __shared__ float sred[8][8];
    int warp = threadIdx.x >> 5, lane = threadIdx.x & 31;
    if (lane == 0)
#pragma unroll
        for (int e = 0; e < 8; e++) sred[warp][e] = acc[e];
    __syncthreads();
    if (threadIdx.x < 8) {
        float s = 0.f;
#pragma unroll
        for (int w = 0; w < 8; w++) s += sred[w][threadIdx.x];
        g_beff[threadIdx.x] = s + bg[threadIdx.x];
    }
}

// ---------------- gating (fp32, unchanged) ----------------
__global__ __launch_bounds__(256) void k_gate(const float* __restrict__ q,
                                              float* __restrict__ gate_out) {
    int warp = threadIdx.x >> 5, lane = threadIdx.x & 31;
    int b = blockIdx.x * 8 + warp;
    const float* qrow = q + (size_t)b * D;
    float acc[8];
#pragma unroll
    for (int e = 0; e < 8; e++) acc[e] = 0.f;
#pragma unroll 4
    for (int i = 0; i < 32; i++) {
        int k = i * 32 + lane;
        float qa = qrow[k];
        const float4* w4 = reinterpret_cast<const float4*>(g_Wvog + (size_t)k * 8);
        float4 w0 = w4[0], w1 = w4[1];
        acc[0] += qa * w0.x; acc[1] += qa * w0.y; acc[2] += qa * w0.z; acc[3] += qa * w0.w;
        acc[4] += qa * w1.x; acc[5] += qa * w1.y; acc[6] += qa * w1.z; acc[7] += qa * w1.w;
    }
#pragma unroll
    for (int off = 16; off > 0; off >>= 1)
#pragma unroll
        for (int e = 0; e < 8; e++) acc[e] += __shfl_xor_sync(0xFFFFFFFFu, acc[e], off);

    __shared__ double simp[8];
    if (threadIdx.x < 8) simp[threadIdx.x] = 0.0;
    __syncthreads();

    if (lane == 0) {
        float l[8];
#pragma unroll
        for (int e = 0; e < 8; e++) l[e] = acc[e] + g_beff[e];
        float m = l[0];
#pragma unroll
        for (int e = 1; e < 8; e++) m = fmaxf(m, l[e]);
        float ex[8], Z = 0.f;
#pragma unroll
        for (int e = 0; e < 8; e++) { ex[e] = expf(l[e] - m); Z += ex[e]; }
        float p[8];
        float invZ = 1.f / Z;
#pragma unroll
        for (int e = 0; e < 8; e++) p[e] = ex[e] * invZ;
#pragma unroll
        for (int e = 0; e < 8; e++) gate_out[(size_t)b * 8 + e] = p[e];

        int e1 = 0;
#pragma unroll
        for (int e = 1; e < 8; e++) if (p[e] > p[e1]) e1 = e;
        int e2 = (e1 == 0) ? 1 : 0;
#pragma unroll
        for (int e = 0; e < 8; e++) if (e != e1 && p[e] > p[e2]) e2 = e;
        float t = expf(p[e2] - p[e1]);
        float inv = 1.f / (1.f + t);
        g_tok_e[2 * b] = e1;  g_tok_e[2 * b + 1] = e2;
        g_tok_w[2 * b] = inv; g_tok_w[2 * b + 1] = t * inv;
        atomicAdd(&g_counts[e1], 1);
        atomicAdd(&g_counts[e2], 1);
#pragma unroll
        for (int e = 0; e < 8; e++) atomicAdd(&simp[e], (double)p[e]);
    }
    __syncthreads();
    if (threadIdx.x < 8) atomicAdd(&g_imp[threadIdx.x], simp[threadIdx.x]);
}

__global__ void k_scan() {
    if (threadIdx.x == 0) {
        int o = 0;
#pragma unroll
        for (int e = 0; e < 8; e++) { g_offsets[e] = o; o += g_counts[e]; }
    }
}

__global__ __launch_bounds__(256) void k_scatter() {
    int b = blockIdx.x * 256 + threadIdx.x;
    if (b >= B_TOK) return;
#pragma unroll
    for (int j = 0; j < 2; j++) {
        int e = g_tok_e[2 * b + j];
        int s = g_offsets[e] + atomicAdd(&g_cursor[e], 1);
        g_slot_tok[s] = b;
        g_slot_w[s] = g_tok_w[2 * b + j];
        g_tok_slot[2 * b + j] = s;
    }
}

// ---------------- convert x -> bf16 hi/lo planes (pair-permuted 16-groups) ----------------
__global__ __launch_bounds__(256) void k_cvt_x(const float* __restrict__ x) {
    int id = blockIdx.x * 256 + threadIdx.x;          // tok*64 + grp
    int tok = id >> 6, grp = id & 63;
    const float* src = x + (size_t)tok * D + grp * 16;
    union { __nv_bfloat16 h[16]; uint4 u[2]; } hi, lo;
#pragma unroll
    for (int k = 0; k < 16; k++) {
        float v = src[k];
        __nv_bfloat16 h = __float2bfloat16(v);
        __nv_bfloat16 l = __float2bfloat16(v - __bfloat162float(h));
        int p = perm16(k);
        hi.h[p] = h; lo.h[p] = l;
    }
    size_t off = (size_t)tok * D + grp * 16;
    reinterpret_cast<uint4*>(g_xhi + off)[0] = hi.u[0];
    reinterpret_cast<uint4*>(g_xhi + off)[1] = hi.u[1];
    reinterpret_cast<uint4*>(g_xlo + off)[0] = lo.u[0];
    reinterpret_cast<uint4*>(g_xlo + off)[1] = lo.u[1];
}

// ---------------- convert+transpose weights -> [e][kt][n][16] bf16 hi/lo ----------------
__global__ __launch_bounds__(256) void k_cvt_w(const float* __restrict__ W1,
                                               const float* __restrict__ W2) {
    const float* W = (blockIdx.y == 0) ? W1 : W2;
    __nv_bfloat16* whi = (blockIdx.y == 0) ? g_w1hi : g_w2hi;
    __nv_bfloat16* wlo = (blockIdx.y == 0) ? g_w1lo : g_w2lo;
    int id = blockIdx.x * 256 + threadIdx.x;          // e*64*1024 + kt*1024 + n
    int e = id >> 16, kt = (id >> 10) & 63, n = id & 1023;
    const float* src = W + ((size_t)e * D + kt * 16) * D + n;
    union { __nv_bfloat16 h[16]; uint4 u[2]; } hi, lo;
#pragma unroll
    for (int k = 0; k < 16; k++) {
        float v = src[(size_t)k * D];
        __nv_bfloat16 h = __float2bfloat16(v);
        __nv_bfloat16 l = __float2bfloat16(v - __bfloat162float(h));
        int p = perm16(k);
        hi.h[p] = h; lo.h[p] = l;
    }
    size_t off = (size_t)id * 16;
    reinterpret_cast<uint4*>(whi + off)[0] = hi.u[0];
    reinterpret_cast<uint4*>(whi + off)[1] = hi.u[1];
    reinterpret_cast<uint4*>(wlo + off)[0] = lo.u[0];
    reinterpret_cast<uint4*>(wlo + off)[1] = lo.u[1];
}

// ---------------- grouped bf16 split GEMM, cp.async 5-stage pipeline ----------------
// 128x128 CTA tile, BK=16, 8 warps (2Mx4N), warp tile 64x32.
// Stage smem (b32): [plane Ahi|Alo|Bhi|Blo][row 0..127][8]   -> 16KB/stage
// MODE 1: h1(hi/lo planes) = silu( gather(x) @ W1 + b1 )
// MODE 2: h2 = slot_w * ( h1 @ W2 + b2 )
template <int MODE>
__global__ __launch_bounds__(256, 1) void k_gemm(const float* __restrict__ bbase) {
    extern __shared__ uint32_t smem[];

    int e = blockIdx.z;
    int M = g_counts[e];
    int m0 = blockIdx.y * 128;
    if (m0 >= M) return;
    int n0 = blockIdx.x * 128;
    int goff = g_offsets[e];
    const float* bp = bbase + (size_t)e * D;

    const __nv_bfloat16* Ahi = (MODE == 1) ? g_xhi : g_h1hi;
    const __nv_bfloat16* Alo = (MODE == 1) ? g_xlo : g_h1lo;
    const __nv_bfloat16* Bhi = (MODE == 1) ? g_w1hi : g_w2hi;
    const __nv_bfloat16* Blo = (MODE == 1) ? g_w1lo : g_w2lo;

    int tid = threadIdx.x;
    int lane = tid & 31, warp = tid >> 5;
    int g = lane >> 2, c4 = lane & 3;
    int wm = warp >> 2, wn = warp & 3;

    // loader mapping: thread -> (row, 16B half) for both A and B
    int rA = tid >> 1, hA = tid & 1;
    int rr = m0 + rA; if (rr > M - 1) rr = M - 1;
    const __nv_bfloat16 *srcAhi, *srcAlo;
    if (MODE == 1) {
        int tok = g_slot_tok[goff + rr];
        srcAhi = Ahi + (size_t)tok * D + hA * 8;
        srcAlo = Alo + (size_t)tok * D + hA * 8;
    } else {
        srcAhi = Ahi + (size_t)(goff + rr) * D + hA * 8;
        srcAlo = Alo + (size_t)(goff + rr) * D + hA * 8;
    }
    const __nv_bfloat16* srcBhi = Bhi + (((size_t)e * NKT) * D + n0 + rA) * 16 + hA * 8;
    const __nv_bfloat16* srcBlo = Blo + (((size_t)e * NKT) * D + n0 + rA) * 16 + hA * 8;

    uint32_t sbase = (uint32_t)__cvta_generic_to_shared(smem);
    uint32_t wAhi = sbase + (rA * 8 + hA * 4) * 4;
    uint32_t wAlo = wAhi + 1024 * 4;
    uint32_t wBhi = wAhi + 2048 * 4;
    uint32_t wBlo = wAhi + 3072 * 4;

#define ISSUE(kt, s)                                                          \
    do {                                                                      \
        uint32_t so = (s) * 16384;                                            \
        cpa16(wAhi + so, srcAhi + (kt) * 16);                                 \
        cpa16(wAlo + so, srcAlo + (kt) * 16);                                 \
        cpa16(wBhi + so, srcBhi + (size_t)(kt) * (D * 16));                   \
        cpa16(wBlo + so, srcBlo + (size_t)(kt) * (D * 16));                   \
        asm volatile("cp.async.commit_group;");                               \
    } while (0)

    float acc[4][4][4];
#pragma unroll
    for (int mt = 0; mt < 4; mt++)
#pragma unroll
        for (int nt = 0; nt < 4; nt++)
#pragma unroll
            for (int i = 0; i < 4; i++) acc[mt][nt][i] = 0.f;

#pragma unroll
    for (int s = 0; s < STAGES - 1; s++) ISSUE(s, s);

    // per-warp smem read bases (b32)
    int aBase = (wm * 64 + g) * 8 + 2 * c4;
    int bBase = 2048 + (wn * 32 + g) * 8 + 2 * c4;

    for (int kt = 0; kt < NKT; kt++) {
        int s = kt % STAGES;
        asm volatile("cp.async.wait_group 3;");
        __syncthreads();
        int pf = kt + STAGES - 1;
        if (pf < NKT) ISSUE(pf, pf % STAGES);

        const uint32_t* st = smem + s * 4096;
        uint32_t bh[4][2], bl[4][2];
#pragma unroll
        for (int nt = 0; nt < 4; nt++) {
            uint2 vh = *reinterpret_cast<const uint2*>(st + bBase + nt * 64);
            uint2 vl = *reinterpret_cast<const uint2*>(st + bBase + nt * 64 + 1024);
            bh[nt][0] = vh.x; bh[nt][1] = vh.y;
            bl[nt][0] = vl.x; bl[nt][1] = vl.y;
        }
#pragma unroll
        for (int mt = 0; mt < 4; mt++) {
            const uint32_t* pa = st + aBase + mt * 128;
            uint2 h0 = *reinterpret_cast<const uint2*>(pa);
            uint2 h1 = *reinterpret_cast<const uint2*>(pa + 64);
            uint2 l0 = *reinterpret_cast<const uint2*>(pa + 1024);
            uint2 l1 = *reinterpret_cast<const uint2*>(pa + 1024 + 64);
            uint32_t ah[4] = {h0.x, h1.x, h0.y, h1.y};
            uint32_t al[4] = {l0.x, l1.x, l0.y, l1.y};
#pragma unroll
            for (int nt = 0; nt < 4; nt++) {
                mma_bf16(acc[mt][nt], ah, bh[nt]);
                mma_bf16(acc[mt][nt], ah, bl[nt]);
                mma_bf16(acc[mt][nt], al, bh[nt]);
            }
        }
    }
#undef ISSUE

    // ---------------- epilogue ----------------
#pragma unroll
    for (int nt = 0; nt < 4; nt++) {
        int j = n0 + wn * 32 + nt * 8 + 2 * c4;      // even col pair (j, j+1)
        float2 bb = *reinterpret_cast<const float2*>(bp + j);
        int grp = j >> 4;
        int pidx = grp * 16 + perm16(j & 15);        // permuted element index of col j
#pragma unroll
        for (int mt = 0; mt < 4; mt++) {
            int r0 = m0 + wm * 64 + mt * 16 + g;
#pragma unroll
            for (int half = 0; half < 2; half++) {
                int gr = r0 + half * 8;
                if (gr >= M) continue;
                float z0 = acc[mt][nt][2 * half] + bb.x;
                float z1 = acc[mt][nt][2 * half + 1] + bb.y;
                if (MODE == 1) {
                    float s0 = z0 / (1.f + expf(-z0));
                    float s1 = z1 / (1.f + expf(-z1));
                    __nv_bfloat16 h0 = __float2bfloat16(s0);
                    __nv_bfloat16 h1 = __float2bfloat16(s1);
                    __nv_bfloat16 l0 = __float2bfloat16(s0 - __bfloat162float(h0));
                    __nv_bfloat16 l1 = __float2bfloat16(s1 - __bfloat162float(h1));
                    size_t off = (size_t)(goff + gr) * D + pidx;
                    *reinterpret_cast<__nv_bfloat162*>(g_h1hi + off) = __nv_bfloat162(h0, h1);
                    *reinterpret_cast<__nv_bfloat162*>(g_h1lo + off) = __nv_bfloat162(l0, l1);
                } else {
                    float wr = g_slot_w[goff + gr];
                    *reinterpret_cast<float2*>(g_h2 + (size_t)(goff + gr) * D + j) =
                        make_float2(wr * z0, wr * z1);
                }
            }
        }
    }
}

// ---------------- combine ----------------
__global__ __launch_bounds__(256) void k_combine(float* __restrict__ y) {
    int idx = blockIdx.x * 256 + threadIdx.x;
    int b = idx >> 8;
    int c = idx & 255;
    const float4* h2 = reinterpret_cast<const float4*>(g_h2);
    float4 u = h2[(size_t)g_tok_slot[2 * b] * 256 + c];
    float4 v = h2[(size_t)g_tok_slot[2 * b + 1] * 256 + c];
    reinterpret_cast<float4*>(y)[idx] = make_float4(u.x + v.x, u.y + v.y, u.z + v.z, u.w + v.w);
}

// ---------------- importance loss ----------------
__global__ void k_loss(float* __restrict__ out) {
    if (threadIdx.x == 0) {
        double s = 0.0;
#pragma unroll
        for (int e = 0; e < 8; e++) s += g_imp[e];
        double mean = s / 8.0;
        double var = 0.0;
#pragma unroll
        for (int e = 0; e < 8; e++) { double d = g_imp[e] - mean; var += d * d; }
        var /= 7.0;
        out[0] = (float)(0.01 * var / (mean * mean));
    }
}

extern "C" void kernel_launch(void* const* d_in, const int* in_sizes, int n_in,
                              void* d_out, int out_size) {
    const float* x  = (const float*)d_in[0];
    const float* q  = (const float*)d_in[1];
    const float* Wv = (const float*)d_in[2];
    const float* bv = (const float*)d_in[3];
    const float* Wo = (const float*)d_in[4];
    const float* bo = (const float*)d_in[5];
    const float* Wg = (const float*)d_in[6];
    const float* bg = (const float*)d_in[7];
    const float* W1 = (const float*)d_in[8];
    const float* b1 = (const float*)d_in[9];
    const float* W2 = (const float*)d_in[10];
    const float* b2 = (const float*)d_in[11];

    float* y        = (float*)d_out;
    float* gate_out = y + (size_t)B_TOK * D;
    float* loss_out = gate_out + (size_t)B_TOK * E_EXP;

    static int smem_set = 0;
    if (!smem_set) {
        cudaFuncSetAttribute(k_gemm<1>, cudaFuncAttributeMaxDynamicSharedMemorySize, SMEM_BYTES);
        cudaFuncSetAttribute(k_gemm<2>, cudaFuncAttributeMaxDynamicSharedMemorySize, SMEM_BYTES);
        smem_set = 1;
    }

    k_zero<<<1, 32>>>();
    k_cvt_x<<<(B_TOK * 64) / 256, 256>>>(x);
    k_cvt_w<<<dim3((E_EXP * NKT * D) / 256, 2), 256>>>(W1, W2);
    k_mat_small<<<D, 256>>>(Wo, Wg, 0);
    k_mat_small<<<D, 256>>>(Wv, nullptr, 1);
    k_beff<<<1, 256>>>(bv, bo, Wg, bg);
    k_gate<<<B_TOK / 8, 256>>>(q, gate_out);
    k_scan<<<1, 32>>>();
    k_scatter<<<B_TOK / 256, 256>>>();
    k_gemm<1><<<dim3(D / 128, B_TOK / 128, E_EXP), 256, SMEM_BYTES>>>(b1);
    k_gemm<2><<<dim3(D / 128, B_TOK / 128, E_EXP), 256, SMEM_BYTES>>>(b2);
    k_combine<<<(B_TOK * D / 4) / 256, 256>>>(y);
    k_loss<<<1, 32>>>(loss_out);
}

// round 6
// speedup vs baseline: 4.2268x; 1.3582x over previous
#include <cuda_runtime.h>
#include <cuda_fp16.h>
#include <cstdint>

#define D 1024
#define B_TOK 16384
#define E_EXP 8
#define NSLOT (2 * B_TOK)
#define NKT (D / 16)            // 64 k-tiles
#define STAGES 5
#define STAGE_BYTES 12288       // A 4K + Bhi 4K + Blo 4K
#define SMEM_BYTES (STAGES * STAGE_BYTES)

// ---------------- scratch: __device__ globals (no allocations allowed) ----------------
__device__ float  g_Wog[D * E_EXP];
__device__ float  g_Wvog[D * E_EXP];
__device__ float  g_beff[E_EXP];
__device__ int    g_tok_e[2 * B_TOK];
__device__ float  g_tok_w[2 * B_TOK];
__device__ int    g_tok_slot[2 * B_TOK];
__device__ int    g_counts[E_EXP];
__device__ int    g_offsets[E_EXP];
__device__ int    g_cursor[E_EXP];
__device__ double g_imp[E_EXP];
__device__ int    g_slot_tok[NSLOT];
__device__ float  g_slot_w[NSLOT];

// activations: single fp16, pair-permuted 16-groups
__device__ __align__(256) __half g_x[(size_t)B_TOK * D];
__device__ __align__(256) __half g_h1[(size_t)NSLOT * D];
// weights: fp16 hi/lo planes, transposed [e][kt][n][16] pair-permuted
__device__ __align__(256) __half g_w1hi[(size_t)E_EXP * NKT * D * 16];
__device__ __align__(256) __half g_w1lo[(size_t)E_EXP * NKT * D * 16];
__device__ __align__(256) __half g_w2hi[(size_t)E_EXP * NKT * D * 16];
__device__ __align__(256) __half g_w2lo[(size_t)E_EXP * NKT * D * 16];
__device__ __align__(256) float g_h2[(size_t)NSLOT * D];

// pair-permuted position of k within a 16-group: pairs stored (0,4,1,5,2,6,3,7)
__device__ __forceinline__ int perm16(int k) {
    int p = k >> 1;
    return (((p & 3) * 2 + (p >> 2)) << 1) + (k & 1);
}

__device__ __forceinline__ void cpa16(uint32_t saddr, const void* g) {
    asm volatile("cp.async.cg.shared.global [%0], [%1], 16;" :: "r"(saddr), "l"(g));
}
__device__ __forceinline__ void mma_f16(float* d, const uint32_t* a, const uint32_t* b) {
    asm("mma.sync.aligned.m16n8k16.row.col.f32.f16.f16.f32 "
        "{%0,%1,%2,%3},{%4,%5,%6,%7},{%8,%9},{%0,%1,%2,%3};"
        : "+f"(d[0]), "+f"(d[1]), "+f"(d[2]), "+f"(d[3])
        : "r"(a[0]), "r"(a[1]), "r"(a[2]), "r"(a[3]), "r"(b[0]), "r"(b[1]));
}

// ---------------- zero ----------------
__global__ void k_zero() {
    int t = threadIdx.x;
    if (t < E_EXP) { g_counts[t] = 0; g_cursor[t] = 0; g_imp[t] = 0.0; }
}

// ---------------- small mats for gating (fp32) ----------------
__global__ __launch_bounds__(256) void k_mat_small(const float* __restrict__ A,
                                                   const float* __restrict__ BmArg,
                                                   int which) {
    const float* Bm = (which == 0) ? BmArg : g_Wog;
    float* out = (which == 0) ? g_Wog : g_Wvog;
    int r = blockIdx.x;
    float acc[8];
#pragma unroll
    for (int e = 0; e < 8; e++) acc[e] = 0.f;
    for (int k = threadIdx.x; k < D; k += 256) {
        float a = A[(size_t)r * D + k];
        const float4* b4 = reinterpret_cast<const float4*>(Bm + (size_t)k * 8);
        float4 b0 = b4[0], b1 = b4[1];
        acc[0] += a * b0.x; acc[1] += a * b0.y; acc[2] += a * b0.z; acc[3] += a * b0.w;
        acc[4] += a * b1.x; acc[5] += a * b1.y; acc[6] += a * b1.z; acc[7] += a * b1.w;
    }
#pragma unroll
    for (int off = 16; off > 0; off >>= 1)
#pragma unroll
        for (int e = 0; e < 8; e++) acc[e] += __shfl_xor_sync(0xFFFFFFFFu, acc[e], off);
    __shared__ float sred[8][8];
    int warp = threadIdx.x >> 5, lane = threadIdx.x & 31;
    if (lane == 0)
#pragma unroll
        for (int e = 0; e < 8; e++) sred[warp][e] = acc[e];
    __syncthreads();
    if (threadIdx.x < 8) {
        float s = 0.f;
#pragma unroll
        for (int w = 0; w < 8; w++) s += sred[w][threadIdx.x];
        out[(size_t)r * 8 + threadIdx.x] = s;
    }
}

__global__ __launch_bounds__(256) void k_beff(const float* __restrict__ bv,
                                              const float* __restrict__ bo,
                                              const float* __restrict__ Wg,
                                              const float* __restrict__ bg) {
    float acc[8];
#pragma unroll
    for (int e = 0; e < 8; e++) acc[e] = 0.f;
    for (int k = threadIdx.x; k < D; k += 256) {
        float a = bv[k], b = bo[k];
        const float4* w4 = reinterpret_cast<const float4*>(g_Wog + (size_t)k * 8);
        const float4* g4 = reinterpret_cast<const float4*>(Wg + (size_t)k * 8);
        float4 w0 = w4[0], w1 = w4[1], g0 = g4[0], g1 = g4[1];
        acc[0] += a * w0.x + b * g0.x; acc[1] += a * w0.y + b * g0.y;
        acc[2] += a * w0.z + b * g0.z; acc[3] += a * w0.w + b * g0.w;
        acc[4] += a * w1.x + b * g1.x; acc[5] += a * w1.y + b * g1.y;
        acc[6] += a * w1.z + b * g1.z; acc[7] += a * w1.w + b * g1.w;
    }
#pragma unroll
    for (int off = 16; off > 0; off >>= 1)
#pragma unroll
        for (int e = 0; e < 8; e++) acc[e] += __shfl_xor_sync(0xFFFFFFFFu, acc[e], off);
    __shared__ float sred[8][8];
    int warp = threadIdx.x >> 5, lane = threadIdx.x & 31;
    if (lane == 0)
#pragma unroll
        for (int e = 0; e < 8; e++) sred[warp][e] = acc[e];
    __syncthreads();
    if (threadIdx.x < 8) {
        float s = 0.f;
#pragma unroll
        for (int w = 0; w < 8; w++) s += sred[w][threadIdx.x];
        g_beff[threadIdx.x] = s + bg[threadIdx.x];
    }
}

// ---------------- gating (fp32, selection-critical — unchanged) ----------------
__global__ __launch_bounds__(256) void k_gate(const float* __restrict__ q,
                                              float* __restrict__ gate_out) {
    int warp = threadIdx.x >> 5, lane = threadIdx.x & 31;
    int b = blockIdx.x * 8 + warp;
    const float* qrow = q + (size_t)b * D;
    float acc[8];
#pragma unroll
    for (int e = 0; e < 8; e++) acc[e] = 0.f;
#pragma unroll 4
    for (int i = 0; i < 32; i++) {
        int k = i * 32 + lane;
        float qa = qrow[k];
        const float4* w4 = reinterpret_cast<const float4*>(g_Wvog + (size_t)k * 8);
        float4 w0 = w4[0], w1 = w4[1];
        acc[0] += qa * w0.x; acc[1] += qa * w0.y; acc[2] += qa * w0.z; acc[3] += qa * w0.w;
        acc[4] += qa * w1.x; acc[5] += qa * w1.y; acc[6] += qa * w1.z; acc[7] += qa * w1.w;
    }
#pragma unroll
    for (int off = 16; off > 0; off >>= 1)
#pragma unroll
        for (int e = 0; e < 8; e++) acc[e] += __shfl_xor_sync(0xFFFFFFFFu, acc[e], off);

    __shared__ double simp[8];
    if (threadIdx.x < 8) simp[threadIdx.x] = 0.0;
    __syncthreads();

    if (lane == 0) {
        float l[8];
#pragma unroll
        for (int e = 0; e < 8; e++) l[e] = acc[e] + g_beff[e];
        float m = l[0];
#pragma unroll
        for (int e = 1; e < 8; e++) m = fmaxf(m, l[e]);
        float ex[8], Z = 0.f;
#pragma unroll
        for (int e = 0; e < 8; e++) { ex[e] = expf(l[e] - m); Z += ex[e]; }
        float p[8];
        float invZ = 1.f / Z;
#pragma unroll
        for (int e = 0; e < 8; e++) p[e] = ex[e] * invZ;
#pragma unroll
        for (int e = 0; e < 8; e++) gate_out[(size_t)b * 8 + e] = p[e];

        int e1 = 0;
#pragma unroll
        for (int e = 1; e < 8; e++) if (p[e] > p[e1]) e1 = e;
        int e2 = (e1 == 0) ? 1 : 0;
#pragma unroll
        for (int e = 0; e < 8; e++) if (e != e1 && p[e] > p[e2]) e2 = e;
        float t = expf(p[e2] - p[e1]);
        float inv = 1.f / (1.f + t);
        g_tok_e[2 * b] = e1;  g_tok_e[2 * b + 1] = e2;
        g_tok_w[2 * b] = inv; g_tok_w[2 * b + 1] = t * inv;
        atomicAdd(&g_counts[e1], 1);
        atomicAdd(&g_counts[e2], 1);
#pragma unroll
        for (int e = 0; e < 8; e++) atomicAdd(&simp[e], (double)p[e]);
    }
    __syncthreads();
    if (threadIdx.x < 8) atomicAdd(&g_imp[threadIdx.x], simp[threadIdx.x]);
}

__global__ void k_scan() {
    if (threadIdx.x == 0) {
        int o = 0;
#pragma unroll
        for (int e = 0; e < 8; e++) { g_offsets[e] = o; o += g_counts[e]; }
    }
}

__global__ __launch_bounds__(256) void k_scatter() {
    int b = blockIdx.x * 256 + threadIdx.x;
    if (b >= B_TOK) return;
#pragma unroll
    for (int j = 0; j < 2; j++) {
        int e = g_tok_e[2 * b + j];
        int s = g_offsets[e] + atomicAdd(&g_cursor[e], 1);
        g_slot_tok[s] = b;
        g_slot_w[s] = g_tok_w[2 * b + j];
        g_tok_slot[2 * b + j] = s;
    }
}

// ---------------- convert x -> single fp16 (pair-permuted 16-groups) ----------------
__global__ __launch_bounds__(256) void k_cvt_x(const float* __restrict__ x) {
    int id = blockIdx.x * 256 + threadIdx.x;          // tok*64 + grp
    int tok = id >> 6, grp = id & 63;
    const float* src = x + (size_t)tok * D + grp * 16;
    union { __half h[16]; uint4 u[2]; } o;
#pragma unroll
    for (int k = 0; k < 16; k++) o.h[perm16(k)] = __float2half_rn(src[k]);
    size_t off = (size_t)tok * D + grp * 16;
    reinterpret_cast<uint4*>(g_x + off)[0] = o.u[0];
    reinterpret_cast<uint4*>(g_x + off)[1] = o.u[1];
}

// ---------------- convert+transpose weights -> [e][kt][n][16] fp16 hi/lo ----------------
__global__ __launch_bounds__(256) void k_cvt_w(const float* __restrict__ W1,
                                               const float* __restrict__ W2) {
    const float* W = (blockIdx.y == 0) ? W1 : W2;
    __half* whi = (blockIdx.y == 0) ? g_w1hi : g_w2hi;
    __half* wlo = (blockIdx.y == 0) ? g_w1lo : g_w2lo;
    int id = blockIdx.x * 256 + threadIdx.x;          // e*64*1024 + kt*1024 + n
    int e = id >> 16, kt = (id >> 10) & 63, n = id & 1023;
    const float* src = W + ((size_t)e * D + kt * 16) * D + n;
    union { __half h[16]; uint4 u[2]; } hi, lo;
#pragma unroll
    for (int k = 0; k < 16; k++) {
        float v = src[(size_t)k * D];
        __half h = __float2half_rn(v);
        __half l = __float2half_rn(v - __half2float(h));
        int p = perm16(k);
        hi.h[p] = h; lo.h[p] = l;
    }
    size_t off = (size_t)id * 16;
    reinterpret_cast<uint4*>(whi + off)[0] = hi.u[0];
    reinterpret_cast<uint4*>(whi + off)[1] = hi.u[1];
    reinterpret_cast<uint4*>(wlo + off)[0] = lo.u[0];
    reinterpret_cast<uint4*>(wlo + off)[1] = lo.u[1];
}

// ---------------- grouped fp16 GEMM, 2-pass weight-split, cp.async 5-stage ----------------
// 128x128 CTA tile, BK=16, 8 warps (2Mx4N), warp tile 64x32, occupancy 2.
// Stage smem (b32): [A | Bhi | Blo] each [128 rows][8 u32] -> 12KB/stage
// MODE 1: h1(fp16) = silu( gather(x) @ (W1hi+W1lo) + b1 )
// MODE 2: h2 = slot_w * ( h1 @ (W2hi+W2lo) + b2 )
template <int MODE>
__global__ __launch_bounds__(256, 2) void k_gemm(const float* __restrict__ bbase) {
    extern __shared__ uint32_t smem[];

    int e = blockIdx.z;
    int M = g_counts[e];
    int m0 = blockIdx.y * 128;
    if (m0 >= M) return;
    int n0 = blockIdx.x * 128;
    int goff = g_offsets[e];
    const float* bp = bbase + (size_t)e * D;

    const __half* Ag   = (MODE == 1) ? g_x : g_h1;
    const __half* Bhig = (MODE == 1) ? g_w1hi : g_w2hi;
    const __half* Blog = (MODE == 1) ? g_w1lo : g_w2lo;

    int tid = threadIdx.x;
    int lane = tid & 31, warp = tid >> 5;
    int g = lane >> 2, c4 = lane & 3;
    int wm = warp >> 2, wn = warp & 3;

    // loader: thread -> (row = tid>>1, 16B half = tid&1) for all 3 planes
    int rA = tid >> 1, hf = tid & 1;
    int rr = m0 + rA; if (rr > M - 1) rr = M - 1;
    const char* srcA;
    if (MODE == 1) srcA = (const char*)(Ag + (size_t)g_slot_tok[goff + rr] * D) + hf * 16;
    else           srcA = (const char*)(Ag + (size_t)(goff + rr) * D) + hf * 16;
    const char* srcBhi = (const char*)(Bhig + (((size_t)e * NKT) * D + n0 + rA) * 16) + hf * 16;
    const char* srcBlo = (const char*)(Blog + (((size_t)e * NKT) * D + n0 + rA) * 16) + hf * 16;

    uint32_t sbase = (uint32_t)__cvta_generic_to_shared(smem);
    uint32_t wA = sbase + tid * 16;

#define ISSUE(kt, s)                                                          \
    do {                                                                      \
        uint32_t so = (s) * STAGE_BYTES;                                      \
        cpa16(wA + so, srcA + (kt) * 32);                                     \
        cpa16(wA + so + 4096, srcBhi + (size_t)(kt) * (D * 32));              \
        cpa16(wA + so + 8192, srcBlo + (size_t)(kt) * (D * 32));              \
        asm volatile("cp.async.commit_group;");                               \
    } while (0)

    float acc[4][4][4];
#pragma unroll
    for (int mt = 0; mt < 4; mt++)
#pragma unroll
        for (int nt = 0; nt < 4; nt++)
#pragma unroll
            for (int i = 0; i < 4; i++) acc[mt][nt][i] = 0.f;

#pragma unroll
    for (int s = 0; s < STAGES - 1; s++) ISSUE(s, s);

    int aBase = (wm * 64 + g) * 8 + 2 * c4;
    int bBase = (wn * 32 + g) * 8 + 2 * c4;

    for (int kt = 0; kt < NKT; kt++) {
        int s = kt % STAGES;
        asm volatile("cp.async.wait_group 3;");
        __syncthreads();
        int pf = kt + STAGES - 1;
        if (pf < NKT) ISSUE(pf, pf % STAGES);

        const uint32_t* st = smem + s * (STAGE_BYTES / 4);
        uint32_t bh[4][2], bl[4][2];
#pragma unroll
        for (int nt = 0; nt < 4; nt++) {
            uint2 vh = *reinterpret_cast<const uint2*>(st + 1024 + bBase + nt * 64);
            uint2 vl = *reinterpret_cast<const uint2*>(st + 2048 + bBase + nt * 64);
            bh[nt][0] = vh.x; bh[nt][1] = vh.y;
            bl[nt][0] = vl.x; bl[nt][1] = vl.y;
        }
#pragma unroll
        for (int mt = 0; mt < 4; mt++) {
            const uint32_t* pa = st + aBase + mt * 128;
            uint2 h0 = *reinterpret_cast<const uint2*>(pa);
            uint2 h1 = *reinterpret_cast<const uint2*>(pa + 64);
            uint32_t ah[4] = {h0.x, h1.x, h0.y, h1.y};
#pragma unroll
            for (int nt = 0; nt < 4; nt++) {
                mma_f16(acc[mt][nt], ah, bh[nt]);
                mma_f16(acc[mt][nt], ah, bl[nt]);
            }
        }
    }
#undef ISSUE

    // ---------------- epilogue ----------------
#pragma unroll
    for (int nt = 0; nt < 4; nt++) {
        int j = n0 + wn * 32 + nt * 8 + 2 * c4;      // even col pair (j, j+1)
        float2 bb = *reinterpret_cast<const float2*>(bp + j);
        int grp = j >> 4;
        int pidx = grp * 16 + perm16(j & 15);        // permuted element index of col j
#pragma unroll
        for (int mt = 0; mt < 4; mt++) {
            int r0 = m0 + wm * 64 + mt * 16 + g;
#pragma unroll
            for (int half = 0; half < 2; half++) {
                int gr = r0 + half * 8;
                if (gr >= M) continue;
                float z0 = acc[mt][nt][2 * half] + bb.x;
                float z1 = acc[mt][nt][2 * half + 1] + bb.y;
                if (MODE == 1) {
                    float s0 = z0 / (1.f + expf(-z0));
                    float s1 = z1 / (1.f + expf(-z1));
                    size_t off = (size_t)(goff + gr) * D + pidx;
                    *reinterpret_cast<__half2*>(g_h1 + off) = __floats2half2_rn(s0, s1);
                } else {
                    float wr = g_slot_w[goff + gr];
                    *reinterpret_cast<float2*>(g_h2 + (size_t)(goff + gr) * D + j) =
                        make_float2(wr * z0, wr * z1);
                }
            }
        }
    }
}

// ---------------- combine ----------------
__global__ __launch_bounds__(256) void k_combine(float* __restrict__ y) {
    int idx = blockIdx.x * 256 + threadIdx.x;
    int b = idx >> 8;
    int c = idx & 255;
    const float4* h2 = reinterpret_cast<const float4*>(g_h2);
    float4 u = h2[(size_t)g_tok_slot[2 * b] * 256 + c];
    float4 v = h2[(size_t)g_tok_slot[2 * b + 1] * 256 + c];
    reinterpret_cast<float4*>(y)[idx] = make_float4(u.x + v.x, u.y + v.y, u.z + v.z, u.w + v.w);
}

// ---------------- importance loss ----------------
__global__ void k_loss(float* __restrict__ out) {
    if (threadIdx.x == 0) {
        double s = 0.0;
#pragma unroll
        for (int e = 0; e < 8; e++) s += g_imp[e];
        double mean = s / 8.0;
        double var = 0.0;
#pragma unroll
        for (int e = 0; e < 8; e++) { double d = g_imp[e] - mean; var += d * d; }
        var /= 7.0;
        out[0] = (float)(0.01 * var / (mean * mean));
    }
}

extern "C" void kernel_launch(void* const* d_in, const int* in_sizes, int n_in,
                              void* d_out, int out_size) {
    const float* x  = (const float*)d_in[0];
    const float* q  = (const float*)d_in[1];
    const float* Wv = (const float*)d_in[2];
    const float* bv = (const float*)d_in[3];
    const float* Wo = (const float*)d_in[4];
    const float* bo = (const float*)d_in[5];
    const float* Wg = (const float*)d_in[6];
    const float* bg = (const float*)d_in[7];
    const float* W1 = (const float*)d_in[8];
    const float* b1 = (const float*)d_in[9];
    const float* W2 = (const float*)d_in[10];
    const float* b2 = (const float*)d_in[11];

    float* y        = (float*)d_out;
    float* gate_out = y + (size_t)B_TOK * D;
    float* loss_out = gate_out + (size_t)B_TOK * E_EXP;

    static int smem_set = 0;
    if (!smem_set) {
        cudaFuncSetAttribute(k_gemm<1>, cudaFuncAttributeMaxDynamicSharedMemorySize, SMEM_BYTES);
        cudaFuncSetAttribute(k_gemm<2>, cudaFuncAttributeMaxDynamicSharedMemorySize, SMEM_BYTES);
        smem_set = 1;
    }

    k_zero<<<1, 32>>>();
    k_cvt_x<<<(B_TOK * 64) / 256, 256>>>(x);
    k_cvt_w<<<dim3((E_EXP * NKT * D) / 256, 2), 256>>>(W1, W2);
    k_mat_small<<<D, 256>>>(Wo, Wg, 0);
    k_mat_small<<<D, 256>>>(Wv, nullptr, 1);
    k_beff<<<1, 256>>>(bv, bo, Wg, bg);
    k_gate<<<B_TOK / 8, 256>>>(q, gate_out);
    k_scan<<<1, 32>>>();
    k_scatter<<<B_TOK / 256, 256>>>();
    k_gemm<1><<<dim3(D / 128, B_TOK / 128, E_EXP), 256, SMEM_BYTES>>>(b1);
    k_gemm<2><<<dim3(D / 128, B_TOK / 128, E_EXP), 256, SMEM_BYTES>>>(b2);
    k_combine<<<(B_TOK * D / 4) / 256, 256>>>(y);
    k_loss<<<1, 32>>>(loss_out);
}

// round 7
// speedup vs baseline: 6.1491x; 1.4548x over previous
#include <cuda_runtime.h>
#include <cuda_fp16.h>
#include <cstdint>

#define D 1024
#define B_TOK 16384
#define E_EXP 8
#define NSLOT (2 * B_TOK)
#define NKT (D / 16)            // 64 k-tiles
#define STAGES 5
#define STAGE_BYTES 8192        // A 4K + B 4K
#define SMEM_BYTES (STAGES * STAGE_BYTES)

// ---------------- scratch: __device__ globals (no allocations allowed) ----------------
__device__ float  g_Wog[D * E_EXP];
__device__ float  g_Wvog[D * E_EXP];
__device__ float  g_beff[E_EXP];
__device__ int    g_tok_e[2 * B_TOK];
__device__ float  g_tok_w[2 * B_TOK];
__device__ int    g_tok_slot[2 * B_TOK];
__device__ int    g_counts[E_EXP];
__device__ int    g_offsets[E_EXP];
__device__ int    g_cursor[E_EXP];
__device__ double g_imp[E_EXP];
__device__ int    g_slot_tok[NSLOT];
__device__ float  g_slot_w[NSLOT];

// activations: single fp16, pair-permuted 16-groups
__device__ __align__(256) __half g_x[(size_t)B_TOK * D];
__device__ __align__(256) __half g_h1[(size_t)NSLOT * D];
// weights: single fp16, transposed [e][kt][n][16] pair-permuted
__device__ __align__(256) __half g_w1[(size_t)E_EXP * NKT * D * 16];
__device__ __align__(256) __half g_w2[(size_t)E_EXP * NKT * D * 16];
__device__ __align__(256) float g_h2[(size_t)NSLOT * D];

// pair-permuted position of k within a 16-group: pairs stored (0,4,1,5,2,6,3,7)
__device__ __forceinline__ int perm16(int k) {
    int p = k >> 1;
    return (((p & 3) * 2 + (p >> 2)) << 1) + (k & 1);
}

__device__ __forceinline__ void cpa16(uint32_t saddr, const void* g) {
    asm volatile("cp.async.cg.shared.global [%0], [%1], 16;" :: "r"(saddr), "l"(g));
}
__device__ __forceinline__ void mma_f16(float* d, const uint32_t* a, const uint32_t* b) {
    asm("mma.sync.aligned.m16n8k16.row.col.f32.f16.f16.f32 "
        "{%0,%1,%2,%3},{%4,%5,%6,%7},{%8,%9},{%0,%1,%2,%3};"
        : "+f"(d[0]), "+f"(d[1]), "+f"(d[2]), "+f"(d[3])
        : "r"(a[0]), "r"(a[1]), "r"(a[2]), "r"(a[3]), "r"(b[0]), "r"(b[1]));
}

// ---------------- zero ----------------
__global__ void k_zero() {
    int t = threadIdx.x;
    if (t < E_EXP) { g_counts[t] = 0; g_cursor[t] = 0; g_imp[t] = 0.0; }
}

// ---------------- small mats for gating (fp32) ----------------
__global__ __launch_bounds__(256) void k_mat_small(const float* __restrict__ A,
                                                   const float* __restrict__ BmArg,
                                                   int which) {
    const float* Bm = (which == 0) ? BmArg : g_Wog;
    float* out = (which == 0) ? g_Wog : g_Wvog;
    int r = blockIdx.x;
    float acc[8];
#pragma unroll
    for (int e = 0; e < 8; e++) acc[e] = 0.f;
    for (int k = threadIdx.x; k < D; k += 256) {
        float a = A[(size_t)r * D + k];
        const float4* b4 = reinterpret_cast<const float4*>(Bm + (size_t)k * 8);
        float4 b0 = b4[0], b1 = b4[1];
        acc[0] += a * b0.x; acc[1] += a * b0.y; acc[2] += a * b0.z; acc[3] += a * b0.w;
        acc[4] += a * b1.x; acc[5] += a * b1.y; acc[6] += a * b1.z; acc[7] += a * b1.w;
    }
#pragma unroll
    for (int off = 16; off > 0; off >>= 1)
#pragma unroll
        for (int e = 0; e < 8; e++) acc[e] += __shfl_xor_sync(0xFFFFFFFFu, acc[e], off);
    __shared__ float sred[8][8];
    int warp = threadIdx.x >> 5, lane = threadIdx.x & 31;
    if (lane == 0)
#pragma unroll
        for (int e = 0; e < 8; e++) sred[warp][e] = acc[e];
    __syncthreads();
    if (threadIdx.x < 8) {
        float s = 0.f;
#pragma unroll
        for (int w = 0; w < 8; w++) s += sred[w][threadIdx.x];
        out[(size_t)r * 8 + threadIdx.x] = s;
    }
}

__global__ __launch_bounds__(256) void k_beff(const float* __restrict__ bv,
                                              const float* __restrict__ bo,
                                              const float* __restrict__ Wg,
                                              const float* __restrict__ bg) {
    float acc[8];
#pragma unroll
    for (int e = 0; e < 8; e++) acc[e] = 0.f;
    for (int k = threadIdx.x; k < D; k += 256) {
        float a = bv[k], b = bo[k];
        const float4* w4 = reinterpret_cast<const float4*>(g_Wog + (size_t)k * 8);
        const float4* g4 = reinterpret_cast<const float4*>(Wg + (size_t)k * 8);
        float4 w0 = w4[0], w1 = w4[1], g0 = g4[0], g1 = g4[1];
        acc[0] += a * w0.x + b * g0.x; acc[1] += a * w0.y + b * g0.y;
        acc[2] += a * w0.z + b * g0.z; acc[3] += a * w0.w + b * g0.w;
        acc[4] += a * w1.x + b * g1.x; acc[5] += a * w1.y + b * g1.y;
        acc[6] += a * w1.z + b * g1.z; acc[7] += a * w1.w + b * g1.w;
    }
#pragma unroll
    for (int off = 16; off > 0; off >>= 1)
#pragma unroll
        for (int e = 0; e < 8; e++) acc[e] += __shfl_xor_sync(0xFFFFFFFFu, acc[e], off);
    __shared__ float sred[8][8];
    int warp = threadIdx.x >> 5, lane = threadIdx.x & 31;
    if (lane == 0)
#pragma unroll
        for (int e = 0; e < 8; e++) sred[warp][e] = acc[e];
    __syncthreads();
    if (threadIdx.x < 8) {
        float s = 0.f;
#pragma unroll
        for (int w = 0; w < 8; w++) s += sred[w][threadIdx.x];
        g_beff[threadIdx.x] = s + bg[threadIdx.x];
    }
}

// ---------------- gating (fp32, selection-critical — unchanged) ----------------
__global__ __launch_bounds__(256) void k_gate(const float* __restrict__ q,
                                              float* __restrict__ gate_out) {
    int warp = threadIdx.x >> 5, lane = threadIdx.x & 31;
    int b = blockIdx.x * 8 + warp;
    const float* qrow = q + (size_t)b * D;
    float acc[8];
#pragma unroll
    for (int e = 0; e < 8; e++) acc[e] = 0.f;
#pragma unroll 4
    for (int i = 0; i < 32; i++) {
        int k = i * 32 + lane;
        float qa = qrow[k];
        const float4* w4 = reinterpret_cast<const float4*>(g_Wvog + (size_t)k * 8);
        float4 w0 = w4[0], w1 = w4[1];
        acc[0] += qa * w0.x; acc[1] += qa * w0.y; acc[2] += qa * w0.z; acc[3] += qa * w0.w;
        acc[4] += qa * w1.x; acc[5] += qa * w1.y; acc[6] += qa * w1.z; acc[7] += qa * w1.w;
    }
#pragma unroll
    for (int off = 16; off > 0; off >>= 1)
#pragma unroll
        for (int e = 0; e < 8; e++) acc[e] += __shfl_xor_sync(0xFFFFFFFFu, acc[e], off);

    __shared__ double simp[8];
    if (threadIdx.x < 8) simp[threadIdx.x] = 0.0;
    __syncthreads();

    if (lane == 0) {
        float l[8];
#pragma unroll
        for (int e = 0; e < 8; e++) l[e] = acc[e] + g_beff[e];
        float m = l[0];
#pragma unroll
        for (int e = 1; e < 8; e++) m = fmaxf(m, l[e]);
        float ex[8], Z = 0.f;
#pragma unroll
        for (int e = 0; e < 8; e++) { ex[e] = expf(l[e] - m); Z += ex[e]; }
        float p[8];
        float invZ = 1.f / Z;
#pragma unroll
        for (int e = 0; e < 8; e++) p[e] = ex[e] * invZ;
#pragma unroll
        for (int e = 0; e < 8; e++) gate_out[(size_t)b * 8 + e] = p[e];

        int e1 = 0;
#pragma unroll
        for (int e = 1; e < 8; e++) if (p[e] > p[e1]) e1 = e;
        int e2 = (e1 == 0) ? 1 : 0;
#pragma unroll
        for (int e = 0; e < 8; e++) if (e != e1 && p[e] > p[e2]) e2 = e;
        float t = expf(p[e2] - p[e1]);
        float inv = 1.f / (1.f + t);
        g_tok_e[2 * b] = e1;  g_tok_e[2 * b + 1] = e2;
        g_tok_w[2 * b] = inv; g_tok_w[2 * b + 1] = t * inv;
        atomicAdd(&g_counts[e1], 1);
        atomicAdd(&g_counts[e2], 1);
#pragma unroll
        for (int e = 0; e < 8; e++) atomicAdd(&simp[e], (double)p[e]);
    }
    __syncthreads();
    if (threadIdx.x < 8) atomicAdd(&g_imp[threadIdx.x], simp[threadIdx.x]);
}

__global__ void k_scan() {
    if (threadIdx.x == 0) {
        int o = 0;
#pragma unroll
        for (int e = 0; e < 8; e++) { g_offsets[e] = o; o += g_counts[e]; }
    }
}

__global__ __launch_bounds__(256) void k_scatter() {
    int b = blockIdx.x * 256 + threadIdx.x;
    if (b >= B_TOK) return;
#pragma unroll
    for (int j = 0; j < 2; j++) {
        int e = g_tok_e[2 * b + j];
        int s = g_offsets[e] + atomicAdd(&g_cursor[e], 1);
        g_slot_tok[s] = b;
        g_slot_w[s] = g_tok_w[2 * b + j];
        g_tok_slot[2 * b + j] = s;
    }
}

// ---------------- convert x -> single fp16 (pair-permuted 16-groups) ----------------
__global__ __launch_bounds__(256) void k_cvt_x(const float* __restrict__ x) {
    int id = blockIdx.x * 256 + threadIdx.x;          // tok*64 + grp
    int tok = id >> 6, grp = id & 63;
    const float* src = x + (size_t)tok * D + grp * 16;
    union { __half h[16]; uint4 u[2]; } o;
#pragma unroll
    for (int k = 0; k < 16; k++) o.h[perm16(k)] = __float2half_rn(src[k]);
    size_t off = (size_t)tok * D + grp * 16;
    reinterpret_cast<uint4*>(g_x + off)[0] = o.u[0];
    reinterpret_cast<uint4*>(g_x + off)[1] = o.u[1];
}

// ---------------- convert+transpose weights -> [e][kt][n][16] fp16 ----------------
__global__ __launch_bounds__(256) void k_cvt_w(const float* __restrict__ W1,
                                               const float* __restrict__ W2) {
    const float* W = (blockIdx.y == 0) ? W1 : W2;
    __half* wdst = (blockIdx.y == 0) ? g_w1 : g_w2;
    int id = blockIdx.x * 256 + threadIdx.x;          // e*64*1024 + kt*1024 + n
    int e = id >> 16, kt = (id >> 10) & 63, n = id & 1023;
    const float* src = W + ((size_t)e * D + kt * 16) * D + n;
    union { __half h[16]; uint4 u[2]; } o;
#pragma unroll
    for (int k = 0; k < 16; k++) o.h[perm16(k)] = __float2half_rn(src[(size_t)k * D]);
    size_t off = (size_t)id * 16;
    reinterpret_cast<uint4*>(wdst + off)[0] = o.u[0];
    reinterpret_cast<uint4*>(wdst + off)[1] = o.u[1];
}

// ---------------- grouped fp16 GEMM, single-pass, cp.async 5-stage ----------------
// 128x128 CTA tile, BK=16, 8 warps (2Mx4N), warp tile 64x32, occupancy 2.
// Stage smem (b32): [A | B] each [128 rows][8 u32] -> 8KB/stage
// MODE 1: h1(fp16) = silu( gather(x) @ W1 + b1 )
// MODE 2: h2 = slot_w * ( h1 @ W2 + b2 )
template <int MODE>
__global__ __launch_bounds__(256, 2) void k_gemm(const float* __restrict__ bbase) {
    extern __shared__ uint32_t smem[];

    int e = blockIdx.z;
    int M = g_counts[e];
    int m0 = blockIdx.y * 128;
    if (m0 >= M) return;
    int n0 = blockIdx.x * 128;
    int goff = g_offsets[e];
    const float* bp = bbase + (size_t)e * D;

    const __half* Ag = (MODE == 1) ? g_x : g_h1;
    const __half* Bg = (MODE == 1) ? g_w1 : g_w2;

    int tid = threadIdx.x;
    int lane = tid & 31, warp = tid >> 5;
    int g = lane >> 2, c4 = lane & 3;
    int wm = warp >> 2, wn = warp & 3;

    // loader: thread -> (row = tid>>1, 16B half = tid&1) for both planes
    int rA = tid >> 1, hf = tid & 1;
    int rr = m0 + rA; if (rr > M - 1) rr = M - 1;
    const char* srcA;
    if (MODE == 1) srcA = (const char*)(Ag + (size_t)g_slot_tok[goff + rr] * D) + hf * 16;
    else           srcA = (const char*)(Ag + (size_t)(goff + rr) * D) + hf * 16;
    const char* srcB = (const char*)(Bg + (((size_t)e * NKT) * D + n0 + rA) * 16) + hf * 16;

    uint32_t sbase = (uint32_t)__cvta_generic_to_shared(smem);
    uint32_t wA = sbase + tid * 16;

#define ISSUE(kt, s)                                                          \
    do {                                                                      \
        uint32_t so = (s) * STAGE_BYTES;                                      \
        cpa16(wA + so, srcA + (kt) * 32);                                     \
        cpa16(wA + so + 4096, srcB + (size_t)(kt) * (D * 32));                \
        asm volatile("cp.async.commit_group;");                               \
    } while (0)

    float acc[4][4][4];
#pragma unroll
    for (int mt = 0; mt < 4; mt++)
#pragma unroll
        for (int nt = 0; nt < 4; nt++)
#pragma unroll
            for (int i = 0; i < 4; i++) acc[mt][nt][i] = 0.f;

#pragma unroll
    for (int s = 0; s < STAGES - 1; s++) ISSUE(s, s);

    int aBase = (wm * 64 + g) * 8 + 2 * c4;
    int bBase = 1024 + (wn * 32 + g) * 8 + 2 * c4;

    for (int kt = 0; kt < NKT; kt++) {
        int s = kt % STAGES;
        asm volatile("cp.async.wait_group 3;");
        __syncthreads();
        int pf = kt + STAGES - 1;
        if (pf < NKT) ISSUE(pf, pf % STAGES);

        const uint32_t* st = smem + s * (STAGE_BYTES / 4);
        uint32_t bh[4][2];
#pragma unroll
        for (int nt = 0; nt < 4; nt++) {
            uint2 vh = *reinterpret_cast<const uint2*>(st + bBase + nt * 64);
            bh[nt][0] = vh.x; bh[nt][1] = vh.y;
        }
#pragma unroll
        for (int mt = 0; mt < 4; mt++) {
            const uint32_t* pa = st + aBase + mt * 128;
            uint2 h0 = *reinterpret_cast<const uint2*>(pa);
            uint2 h1 = *reinterpret_cast<const uint2*>(pa + 64);
            uint32_t ah[4] = {h0.x, h1.x, h0.y, h1.y};
#pragma unroll
            for (int nt = 0; nt < 4; nt++) {
                mma_f16(acc[mt][nt], ah, bh[nt]);
            }
        }
    }
#undef ISSUE

    // ---------------- epilogue ----------------
#pragma unroll
    for (int nt = 0; nt < 4; nt++) {
        int j = n0 + wn * 32 + nt * 8 + 2 * c4;      // even col pair (j, j+1)
        float2 bb = *reinterpret_cast<const float2*>(bp + j);
        int grp = j >> 4;
        int pidx = grp * 16 + perm16(j & 15);        // permuted element index of col j
#pragma unroll
        for (int mt = 0; mt < 4; mt++) {
            int r0 = m0 + wm * 64 + mt * 16 + g;
#pragma unroll
            for (int half = 0; half < 2; half++) {
                int gr = r0 + half * 8;
                if (gr >= M) continue;
                float z0 = acc[mt][nt][2 * half] + bb.x;
                float z1 = acc[mt][nt][2 * half + 1] + bb.y;
                if (MODE == 1) {
                    float s0 = z0 / (1.f + expf(-z0));
                    float s1 = z1 / (1.f + expf(-z1));
                    size_t off = (size_t)(goff + gr) * D + pidx;
                    *reinterpret_cast<__half2*>(g_h1 + off) = __floats2half2_rn(s0, s1);
                } else {
                    float wr = g_slot_w[goff + gr];
                    *reinterpret_cast<float2*>(g_h2 + (size_t)(goff + gr) * D + j) =
                        make_float2(wr * z0, wr * z1);
                }
            }
        }
    }
}

// ---------------- combine ----------------
__global__ __launch_bounds__(256) void k_combine(float* __restrict__ y) {
    int idx = blockIdx.x * 256 + threadIdx.x;
    int b = idx >> 8;
    int c = idx & 255;
    const float4* h2 = reinterpret_cast<const float4*>(g_h2);
    float4 u = h2[(size_t)g_tok_slot[2 * b] * 256 + c];
    float4 v = h2[(size_t)g_tok_slot[2 * b + 1] * 256 + c];
    reinterpret_cast<float4*>(y)[idx] = make_float4(u.x + v.x, u.y + v.y, u.z + v.z, u.w + v.w);
}

// ---------------- importance loss ----------------
__global__ void k_loss(float* __restrict__ out) {
    if (threadIdx.x == 0) {
        double s = 0.0;
#pragma unroll
        for (int e = 0; e < 8; e++) s += g_imp[e];
        double mean = s / 8.0;
        double var = 0.0;
#pragma unroll
        for (int e = 0; e < 8; e++) { double d = g_imp[e] - mean; var += d * d; }
        var /= 7.0;
        out[0] = (float)(0.01 * var / (mean * mean));
    }
}

extern "C" void kernel_launch(void* const* d_in, const int* in_sizes, int n_in,
                              void* d_out, int out_size) {
    const float* x  = (const float*)d_in[0];
    const float* q  = (const float*)d_in[1];
    const float* Wv = (const float*)d_in[2];
    const float* bv = (const float*)d_in[3];
    const float* Wo = (const float*)d_in[4];
    const float* bo = (const float*)d_in[5];
    const float* Wg = (const float*)d_in[6];
    const float* bg = (const float*)d_in[7];
    const float* W1 = (const float*)d_in[8];
    const float* b1 = (const float*)d_in[9];
    const float* W2 = (const float*)d_in[10];
    const float* b2 = (const float*)d_in[11];

    float* y        = (float*)d_out;
    float* gate_out = y + (size_t)B_TOK * D;
    float* loss_out = gate_out + (size_t)B_TOK * E_EXP;

    static int smem_set = 0;
    if (!smem_set) {
        cudaFuncSetAttribute(k_gemm<1>, cudaFuncAttributeMaxDynamicSharedMemorySize, SMEM_BYTES);
        cudaFuncSetAttribute(k_gemm<2>, cudaFuncAttributeMaxDynamicSharedMemorySize, SMEM_BYTES);
        smem_set = 1;
    }

    k_zero<<<1, 32>>>();
    k_cvt_x<<<(B_TOK * 64) / 256, 256>>>(x);
    k_cvt_w<<<dim3((E_EXP * NKT * D) / 256, 2), 256>>>(W1, W2);
    k_mat_small<<<D, 256>>>(Wo, Wg, 0);
    k_mat_small<<<D, 256>>>(Wv, nullptr, 1);
    k_beff<<<1, 256>>>(bv, bo, Wg, bg);
    k_gate<<<B_TOK / 8, 256>>>(q, gate_out);
    k_scan<<<1, 32>>>();
    k_scatter<<<B_TOK / 256, 256>>>();
    k_gemm<1><<<dim3(D / 128, B_TOK / 128, E_EXP), 256, SMEM_BYTES>>>(b1);
    k_gemm<2><<<dim3(D / 128, B_TOK / 128, E_EXP), 256, SMEM_BYTES>>>(b2);
    k_combine<<<(B_TOK * D / 4) / 256, 256>>>(y);
    k_loss<<<1, 32>>>(loss_out);
}